// round 3
// baseline (speedup 1.0000x reference)
#include <cuda_runtime.h>

// ---------------------------------------------------------------------------
// Problem constants (shapes fixed by the reference; N/E/G derived at launch)
// ---------------------------------------------------------------------------
#define NH    4          // heads
#define CH    64         // channels per head
#define HC    256        // NH*CH
#define NIN   300
#define NOUT  768
#define MAXN  50048
#define MAXG  1024
#define SLOPE_ATT 0.2f
#define SLOPE_ACT 0.01f

// ---------------------------------------------------------------------------
// Scratch (device globals; no allocation allowed)
// ---------------------------------------------------------------------------
__device__ float    g_h[MAXN * HC];       // node features after lin  [N, HC]
__device__ float    g_o[MAXN * HC];       // unnormalized aggregation [N, HC]
__device__ float    g_asrc[MAXN * NH];
__device__ float    g_adst[MAXN * NH];
__device__ unsigned g_emax[MAXN * NH];    // ordered-uint encoded max
__device__ float    g_den[MAXN * NH];     // softmax denom (unnormalized sums)
__device__ float    g_pool[MAXG * HC];
__device__ float    g_cnt[MAXG];

// ---------------------------------------------------------------------------
// Helpers
// ---------------------------------------------------------------------------
__device__ __forceinline__ float lrelu(float v, float s) { return v > 0.0f ? v : s * v; }

// order-preserving float <-> uint encoding for atomicMax over floats
__device__ __forceinline__ unsigned fenc(float f) {
    unsigned u = __float_as_uint(f);
    return (u & 0x80000000u) ? ~u : (u | 0x80000000u);
}
__device__ __forceinline__ float fdec(unsigned e) {
    unsigned u = (e & 0x80000000u) ? (e ^ 0x80000000u) : ~e;
    return __uint_as_float(u);
}

__device__ __forceinline__ unsigned long long pack2(float lo, float hi) {
    unsigned long long r;
    asm("mov.b64 %0, {%1, %2};" : "=l"(r) : "f"(lo), "f"(hi));
    return r;
}
__device__ __forceinline__ float2 unpack2(unsigned long long v) {
    float2 f;
    asm("mov.b64 {%0, %1}, %2;" : "=f"(f.x), "=f"(f.y) : "l"(v));
    return f;
}
// packed dual-FMA: acc(2xf32) += a(2xf32) * b(2xf32)   (sm_100+)
__device__ __forceinline__ void ffma2(unsigned long long& acc,
                                      unsigned long long a, unsigned long long b) {
    asm("fma.rn.f32x2 %0, %1, %2, %0;" : "+l"(acc) : "l"(a), "l"(b));
}
__device__ __forceinline__ void red_add_v4(float* p, float4 v) {
    asm volatile("red.global.add.v4.f32 [%0], {%1, %2, %3, %4};"
                 :: "l"(p), "f"(v.x), "f"(v.y), "f"(v.z), "f"(v.w) : "memory");
}

// ---------------------------------------------------------------------------
// K1: h = x @ lin_w   (M=N nodes, K=300, Ncols=256)
// 128x128 block tile, BK=8, 256 threads, 8x8 micro-tile with f32x2 FMAs
// ---------------------------------------------------------------------------
__global__ void __launch_bounds__(256) k_gemm_feat(const float* __restrict__ x,
                                                   const float* __restrict__ w,
                                                   int Ntot) {
    __shared__ float As[8][128];
    __shared__ float Bs[8][128];

    const int t  = threadIdx.x;
    const int m0 = blockIdx.x * 128;
    const int n0 = blockIdx.y * 128;
    const int tx = t & 15;           // 0..15 -> 8 cols each
    const int ty = t >> 4;           // 0..15 -> 8 rows each

    // A-load mapping: 256 float4 loads cover 128 rows x 8 k
    const int lm = t >> 1;           // row within tile
    const int lv = t & 1;            // k sub-quad
    // B-load mapping: 256 float4 loads cover 8 k x 128 cols
    const int kin = t >> 5;          // 0..7
    const int c4  = t & 31;          // 0..31 -> col = c4*4

    unsigned long long acc[8][4];
#pragma unroll
    for (int i = 0; i < 8; i++)
#pragma unroll
        for (int j = 0; j < 4; j++) acc[i][j] = 0ull;

    const int nk = (NIN + 7) / 8;    // 38

    float4 ra, rb;
    // prefetch tile 0
    {
        const int k = lv * 4;
        const int m = m0 + lm;
        ra = make_float4(0.f, 0.f, 0.f, 0.f);
        if (m < Ntot) {
            if (k + 3 < NIN) ra = *(const float4*)(x + (size_t)m * NIN + k);
        }
        rb = make_float4(0.f, 0.f, 0.f, 0.f);
        if (kin < NIN) rb = *(const float4*)(w + (size_t)kin * HC + n0 + c4 * 4);
    }

    for (int kt = 0; kt < nk; kt++) {
        __syncthreads();
        // store current tile
        As[lv * 4 + 0][lm] = ra.x;
        As[lv * 4 + 1][lm] = ra.y;
        As[lv * 4 + 2][lm] = ra.z;
        As[lv * 4 + 3][lm] = ra.w;
        ((float4*)&Bs[kin][0])[c4] = rb;
        __syncthreads();

        // prefetch next tile
        if (kt + 1 < nk) {
            const int k0 = (kt + 1) * 8;
            const int ka = k0 + lv * 4;
            const int m  = m0 + lm;
            ra = make_float4(0.f, 0.f, 0.f, 0.f);
            if (m < Ntot) {
                if (ka + 3 < NIN) {
                    ra = *(const float4*)(x + (size_t)m * NIN + ka);
                } else {
                    float* rv = &ra.x;
#pragma unroll
                    for (int j = 0; j < 4; j++)
                        if (ka + j < NIN) rv[j] = x[(size_t)m * NIN + ka + j];
                }
            }
            const int kb = k0 + kin;
            rb = make_float4(0.f, 0.f, 0.f, 0.f);
            if (kb < NIN) rb = *(const float4*)(w + (size_t)kb * HC + n0 + c4 * 4);
        }

        // compute on current tile
#pragma unroll
        for (int k = 0; k < 8; k++) {
            float4 a0 = *(const float4*)&As[k][ty * 8];
            float4 a1 = *(const float4*)&As[k][ty * 8 + 4];
            float4 b0 = *(const float4*)&Bs[k][tx * 8];
            float4 b1 = *(const float4*)&Bs[k][tx * 8 + 4];
            unsigned long long bp[4] = {pack2(b0.x, b0.y), pack2(b0.z, b0.w),
                                        pack2(b1.x, b1.y), pack2(b1.z, b1.w)};
            float am[8] = {a0.x, a0.y, a0.z, a0.w, a1.x, a1.y, a1.z, a1.w};
#pragma unroll
            for (int i = 0; i < 8; i++) {
                unsigned long long ap = pack2(am[i], am[i]);
#pragma unroll
                for (int j = 0; j < 4; j++) ffma2(acc[i][j], ap, bp[j]);
            }
        }
    }

    // epilogue
#pragma unroll
    for (int i = 0; i < 8; i++) {
        const int m = m0 + ty * 8 + i;
        if (m >= Ntot) continue;
        float* dst = g_h + (size_t)m * HC + n0 + tx * 8;
        float2 c01 = unpack2(acc[i][0]);
        float2 c23 = unpack2(acc[i][1]);
        float2 c45 = unpack2(acc[i][2]);
        float2 c67 = unpack2(acc[i][3]);
        ((float4*)dst)[0] = make_float4(c01.x, c01.y, c23.x, c23.y);
        ((float4*)dst)[1] = make_float4(c45.x, c45.y, c67.x, c67.y);
    }
}

// ---------------------------------------------------------------------------
// K2: per-node attention logits a_src/a_dst + emax init with self-loop logit
// one warp per node; lane l handles 8 channels of head l/8
// ---------------------------------------------------------------------------
__global__ void k_node_att(const float* __restrict__ att_src,
                           const float* __restrict__ att_dst, int Ntot) {
    const int n    = (blockIdx.x * blockDim.x + threadIdx.x) >> 5;
    const int lane = threadIdx.x & 31;
    if (n >= Ntot) return;
    const int head = lane >> 3;
    const int ch   = head * CH + (lane & 7) * 8;

    const float4* hp = (const float4*)(g_h + (size_t)n * HC + ch);
    float4 h0 = hp[0], h1 = hp[1];
    const float4* sp = (const float4*)(att_src + ch);
    const float4* dp = (const float4*)(att_dst + ch);
    float4 s0 = sp[0], s1 = sp[1];
    float4 d0 = dp[0], d1 = dp[1];

    float s = h0.x * s0.x + h0.y * s0.y + h0.z * s0.z + h0.w * s0.w +
              h1.x * s1.x + h1.y * s1.y + h1.z * s1.z + h1.w * s1.w;
    float d = h0.x * d0.x + h0.y * d0.y + h0.z * d0.z + h0.w * d0.w +
              h1.x * d1.x + h1.y * d1.y + h1.z * d1.z + h1.w * d1.w;
#pragma unroll
    for (int m = 1; m < 8; m <<= 1) {
        s += __shfl_xor_sync(0xffffffffu, s, m);
        d += __shfl_xor_sync(0xffffffffu, d, m);
    }
    if ((lane & 7) == 0) {
        g_asrc[n * NH + head] = s;
        g_adst[n * NH + head] = d;
        // self-loop logit seeds the segment max (every node has a self-loop)
        g_emax[n * NH + head] = fenc(lrelu(s + d, SLOPE_ATT));
    }
}

// ---------------------------------------------------------------------------
// K3: per-edge segment max (atomicMax on encoded floats), 1 thread/edge
// ---------------------------------------------------------------------------
__global__ void k_edge_max(const int* __restrict__ ei, int E) {
    const int e = blockIdx.x * blockDim.x + threadIdx.x;
    if (e >= E) return;
    const int s = ei[e];
    const int d = ei[E + e];
    float4 as = *(const float4*)(g_asrc + s * NH);
    float4 ad = *(const float4*)(g_adst + d * NH);
    unsigned* em = g_emax + d * NH;
    atomicMax(em + 0, fenc(lrelu(as.x + ad.x, SLOPE_ATT)));
    atomicMax(em + 1, fenc(lrelu(as.y + ad.y, SLOPE_ATT)));
    atomicMax(em + 2, fenc(lrelu(as.z + ad.z, SLOPE_ATT)));
    atomicMax(em + 3, fenc(lrelu(as.w + ad.w, SLOPE_ATT)));
}

// ---------------------------------------------------------------------------
// K4: node init — self-loop contribution to denom and message accumulator
// one warp per node
// ---------------------------------------------------------------------------
__global__ void k_node_init(int Ntot) {
    const int n    = (blockIdx.x * blockDim.x + threadIdx.x) >> 5;
    const int lane = threadIdx.x & 31;
    if (n >= Ntot) return;
    const int head = lane >> 3;
    const int ch   = head * CH + (lane & 7) * 8;

    float s = g_asrc[n * NH + head];
    float d = g_adst[n * NH + head];
    float v = lrelu(s + d, SLOPE_ATT);
    float m = fdec(g_emax[n * NH + head]);
    float ee = expf(v - m);
    if ((lane & 7) == 0) g_den[n * NH + head] = ee;

    const float4* hp = (const float4*)(g_h + (size_t)n * HC + ch);
    float4 h0 = hp[0], h1 = hp[1];
    float4* op = (float4*)(g_o + (size_t)n * HC + ch);
    op[0] = make_float4(h0.x * ee, h0.y * ee, h0.z * ee, h0.w * ee);
    op[1] = make_float4(h1.x * ee, h1.y * ee, h1.z * ee, h1.w * ee);
}

// ---------------------------------------------------------------------------
// K5: edge aggregation — one warp per edge; fused denom + message scatter
// ---------------------------------------------------------------------------
__global__ void k_edge_agg(const int* __restrict__ ei, int E) {
    const int e    = (blockIdx.x * blockDim.x + threadIdx.x) >> 5;
    const int lane = threadIdx.x & 31;
    if (e >= E) return;
    const int s = ei[e];
    const int d = ei[E + e];
    const int head = lane >> 3;
    const int ch   = head * CH + (lane & 7) * 8;

    float av = g_asrc[s * NH + head] + g_adst[d * NH + head];
    float v  = lrelu(av, SLOPE_ATT);
    float m  = fdec(g_emax[d * NH + head]);
    float ee = expf(v - m);
    if ((lane & 7) == 0) atomicAdd(&g_den[d * NH + head], ee);

    const float4* hp = (const float4*)(g_h + (size_t)s * HC + ch);
    float4 h0 = hp[0], h1 = hp[1];
    float* op = g_o + (size_t)d * HC + ch;
    red_add_v4(op,     make_float4(h0.x * ee, h0.y * ee, h0.z * ee, h0.w * ee));
    red_add_v4(op + 4, make_float4(h1.x * ee, h1.y * ee, h1.z * ee, h1.w * ee));
}

// ---------------------------------------------------------------------------
// K6: zero pooled accumulators
// ---------------------------------------------------------------------------
__global__ void k_pool_zero(int G) {
    const int i = blockIdx.x * blockDim.x + threadIdx.x;
    if (i < G * HC) g_pool[i] = 0.0f;
    if (i < G) g_cnt[i] = 0.0f;
}

// ---------------------------------------------------------------------------
// K7: node finalize (normalize + bias + leaky) and global mean-pool scatter
// one warp per node
// ---------------------------------------------------------------------------
__global__ void k_node_pool(const int* __restrict__ batch,
                            const float* __restrict__ bias, int Ntot) {
    const int n    = (blockIdx.x * blockDim.x + threadIdx.x) >> 5;
    const int lane = threadIdx.x & 31;
    if (n >= Ntot) return;
    const int head = lane >> 3;
    const int ch   = head * CH + (lane & 7) * 8;

    float den = g_den[n * NH + head];
    const float4* op = (const float4*)(g_o + (size_t)n * HC + ch);
    float4 o0 = op[0], o1 = op[1];
    const float4* bp = (const float4*)(bias + ch);
    float4 b0 = bp[0], b1 = bp[1];

    float inv = 1.0f / den;
    o0 = make_float4(lrelu(o0.x * inv + b0.x, SLOPE_ACT),
                     lrelu(o0.y * inv + b0.y, SLOPE_ACT),
                     lrelu(o0.z * inv + b0.z, SLOPE_ACT),
                     lrelu(o0.w * inv + b0.w, SLOPE_ACT));
    o1 = make_float4(lrelu(o1.x * inv + b1.x, SLOPE_ACT),
                     lrelu(o1.y * inv + b1.y, SLOPE_ACT),
                     lrelu(o1.z * inv + b1.z, SLOPE_ACT),
                     lrelu(o1.w * inv + b1.w, SLOPE_ACT));

    const int b = batch[n];
    float* pp = g_pool + (size_t)b * HC + ch;
    red_add_v4(pp,     o0);
    red_add_v4(pp + 4, o1);
    if (lane == 0) atomicAdd(&g_cnt[b], 1.0f);
}

// ---------------------------------------------------------------------------
// K8: final GEMM  out[G,768] = (pool/cnt) @ fc1_w + fc1_b
// block: 16 graphs x 128 outputs, 256 threads
// ---------------------------------------------------------------------------
__global__ void __launch_bounds__(256) k_final(const float* __restrict__ fw,
                                               const float* __restrict__ fb,
                                               float* __restrict__ out, int G) {
    __shared__ float p[16][HC];
    const int g0 = blockIdx.x * 16;
    const int j0 = blockIdx.y * 128;
    const int t  = threadIdx.x;

    for (int i = t; i < 16 * HC; i += 256) {
        const int g = i / HC, k = i % HC;
        float val = 0.0f;
        if (g0 + g < G) {
            float c = fmaxf(g_cnt[g0 + g], 1.0f);
            val = g_pool[(size_t)(g0 + g) * HC + k] / c;
        }
        p[g][k] = val;
    }
    __syncthreads();

    const int j  = j0 + (t & 127);
    const int gg = t >> 7;   // 0 or 1
    float acc[8];
#pragma unroll
    for (int r = 0; r < 8; r++) acc[r] = 0.0f;

    for (int k = 0; k < HC; k++) {
        float wv = fw[(size_t)k * NOUT + j];
#pragma unroll
        for (int r = 0; r < 8; r++) acc[r] += p[gg + r * 2][k] * wv;
    }
    float bv = fb[j];
#pragma unroll
    for (int r = 0; r < 8; r++) {
        const int g = g0 + gg + r * 2;
        if (g < G) out[(size_t)g * NOUT + j] = acc[r] + bv;
    }
}

// ---------------------------------------------------------------------------
// launch
// ---------------------------------------------------------------------------
extern "C" void kernel_launch(void* const* d_in, const int* in_sizes, int n_in,
                              void* d_out, int out_size) {
    const float* x       = (const float*)d_in[0];
    const int*   ei      = (const int*)d_in[1];
    const int*   batch   = (const int*)d_in[2];
    const float* lin_w   = (const float*)d_in[3];
    const float* att_src = (const float*)d_in[4];
    const float* att_dst = (const float*)d_in[5];
    const float* bias    = (const float*)d_in[6];
    const float* fc1_w   = (const float*)d_in[7];
    const float* fc1_b   = (const float*)d_in[8];
    float* out = (float*)d_out;

    const int N = in_sizes[0] / NIN;
    const int E = in_sizes[1] / 2;
    const int G = out_size / NOUT;

    const int nodeBlocks = (N + 7) / 8;     // 8 warps/block, 1 warp/node

    dim3 gemm_grid((N + 127) / 128, HC / 128);
    k_gemm_feat<<<gemm_grid, 256>>>(x, lin_w, N);
    k_node_att<<<nodeBlocks, 256>>>(att_src, att_dst, N);
    k_edge_max<<<(E + 255) / 256, 256>>>(ei, E);
    k_node_init<<<nodeBlocks, 256>>>(N);
    k_edge_agg<<<(E + 7) / 8, 256>>>(ei, E);
    k_pool_zero<<<(G * HC + 255) / 256, 256>>>(G);
    k_node_pool<<<nodeBlocks, 256>>>(batch, bias, N);
    dim3 fin_grid((G + 15) / 16, NOUT / 128);
    k_final<<<fin_grid, 256>>>(fc1_w, fc1_b, out, G);
}